// round 9
// baseline (speedup 1.0000x reference)
#include <cuda_runtime.h>
#include <cuda_bf16.h>
#include <math.h>
#include <stdint.h>

#define B_ 8
#define L_ 4096
#define D_ 1024
#define M_ (B_ * L_)      // 32768
#define K_ D_             // 1024

// GEMM tiling (HMMA warp-level)
#define BM 64
#define BN 64             // per-output (G and H each) N tile
#define BK 32
#define NKT (K_ / BK)     // 32
#define NTH 256
#define NSTAGE 3

#define ROWB 80           // padded SMEM row stride bytes (64B data + 16B pad)
#define TILE_B (64 * ROWB)               // 5120 per tensor tile
#define STAGE (6 * TILE_B)               // 30720
#define DYNSM (NSTAGE * STAGE)           // 92160

// stage-internal offsets
#define OXH 0
#define OXL (1 * TILE_B)
#define OGH (2 * TILE_B)
#define OGL (3 * TILE_B)
#define OHH (4 * TILE_B)
#define OHL (5 * TILE_B)

// epilogue SMEM staging stride (floats)
#define EPS 68

// scan segmentation (segment = one GEMM M-tile)
#define NSEG 64
#define TSEG (L_ / NSEG)  // 64

// ---------------- device scratch (no allocs allowed) ----------------
__device__ __nv_bfloat16 g_xh[(size_t)M_ * K_];
__device__ __nv_bfloat16 g_xl[(size_t)M_ * K_];
__device__ __nv_bfloat16 g_wgh[(size_t)D_ * K_];
__device__ __nv_bfloat16 g_wgl[(size_t)D_ * K_];
__device__ __nv_bfloat16 g_whh[(size_t)D_ * K_];
__device__ __nv_bfloat16 g_whl[(size_t)D_ * K_];
__device__ float g_a[(size_t)M_ * D_];
__device__ float g_b[(size_t)M_ * D_];
__device__ float g_sA[B_ * NSEG * D_];
__device__ float g_sB[B_ * NSEG * D_];
__device__ float g_pA[B_ * NSEG * D_];
__device__ float g_pB[B_ * NSEG * D_];

// ---------------- helpers ----------------
__device__ __forceinline__ uint32_t smem_u32(const void* p) {
    uint32_t a;
    asm("{ .reg .u64 t; cvta.to.shared.u64 t, %1; cvt.u32.u64 %0, t; }" : "=r"(a) : "l"(p));
    return a;
}
__device__ __forceinline__ void cp16(uint32_t dst, const void* src) {
    asm volatile("cp.async.cg.shared.global [%0], [%1], 16;" :: "r"(dst), "l"(src));
}
__device__ __forceinline__ void ldsm4(uint32_t* r, uint32_t addr) {
    asm volatile("ldmatrix.sync.aligned.m8n8.x4.shared.b16 {%0,%1,%2,%3}, [%4];"
                 : "=r"(r[0]), "=r"(r[1]), "=r"(r[2]), "=r"(r[3]) : "r"(addr));
}
__device__ __forceinline__ void mma_bf16(float* d, const uint32_t* a, const uint32_t* b) {
    asm volatile("mma.sync.aligned.m16n8k16.row.col.f32.bf16.bf16.f32 "
                 "{%0,%1,%2,%3}, {%4,%5,%6,%7}, {%8,%9}, {%0,%1,%2,%3};"
                 : "+f"(d[0]), "+f"(d[1]), "+f"(d[2]), "+f"(d[3])
                 : "r"(a[0]), "r"(a[1]), "r"(a[2]), "r"(a[3]), "r"(b[0]), "r"(b[1]));
}

// ---------------------------------------------------------------------------
// Split fp32 -> bf16 hi/lo. tag: 0=x, 1=Wg, 2=Wh
// ---------------------------------------------------------------------------
__global__ void split_kernel(const float* __restrict__ src, int tag, int n4)
{
    int i = blockIdx.x * blockDim.x + threadIdx.x;
    if (i >= n4) return;
    __nv_bfloat16* hi;
    __nv_bfloat16* lo;
    if (tag == 0)      { hi = g_xh;  lo = g_xl;  }
    else if (tag == 1) { hi = g_wgh; lo = g_wgl; }
    else               { hi = g_whh; lo = g_whl; }

    float4 v = ((const float4*)src)[i];
    float f[4] = {v.x, v.y, v.z, v.w};
    __nv_bfloat16 h[4], l[4];
#pragma unroll
    for (int j = 0; j < 4; ++j) {
        __nv_bfloat16 hb = __float2bfloat16(f[j]);
        h[j] = hb;
        l[j] = __float2bfloat16(f[j] - __bfloat162float(hb));
    }
    ((uint2*)hi)[i] = *(uint2*)h;
    ((uint2*)lo)[i] = *(uint2*)l;
}

// ---------------------------------------------------------------------------
// HMMA dual GEMM + activations + fused per-segment scan reduction
//   Dg = x @ Wg^T ; Dh = x @ Wh^T   (3-term bf16 split, fp32 accum)
//   a = sigmoid(Dg + bg) ; b = (1-a) * tanh(Dh + bh)
//   also emits (prod a, fold b) over the 64-row tile (one sub-segment)
// ---------------------------------------------------------------------------
__global__ void __launch_bounds__(NTH, 2)
gemm_mma(const float* __restrict__ bg, const float* __restrict__ bh)
{
    extern __shared__ char smem[];
    __shared__ float s_bg[BN], s_bh[BN];

    const int tid   = threadIdx.x;
    const int wid   = tid >> 5;
    const int lane  = tid & 31;
    const int warpM = wid & 1;         // 0..1 -> m rows 32*warpM
    const int warpN = wid >> 1;        // 0..3 -> n cols 16*warpN
    const int m0 = blockIdx.y * BM;
    const int n0 = blockIdx.x * BN;

    if (tid < BN)            s_bg[tid]      = bg[n0 + tid];
    else if (tid < 2 * BN)   s_bh[tid - BN] = bh[n0 + tid - BN];

    const uint32_t sbase = smem_u32(smem);

    // ldmatrix per-lane offsets
    const int mat = lane >> 3;
    const int lr  = lane & 7;
    // A x4: mats = (m0-7,k0-7),(m8-15,k0-7),(m0-7,k8-15),(m8-15,k8-15)
    const uint32_t aoff = (uint32_t)((warpM * 32 + (mat & 1) * 8 + lr) * ROWB + (mat >> 1) * 16);
    // B x4: mats = (n0-7,k0-7),(n0-7,k8-15),(n8-15,k0-7),(n8-15,k8-15)
    const uint32_t boff = (uint32_t)((warpN * 16 + (mat >> 1) * 8 + lr) * ROWB + (mat & 1) * 16);

    float accG[2][2][4], accH[2][2][4];
#pragma unroll
    for (int h = 0; h < 2; ++h)
#pragma unroll
        for (int q = 0; q < 2; ++q)
#pragma unroll
            for (int r = 0; r < 4; ++r) { accG[h][q][r] = 0.f; accH[h][q][r] = 0.f; }

    // loader: each thread does exactly one 16B chunk per tensor (64 rows x 4 chunks)
    const int lrow = tid >> 2;
    const int lc   = tid & 3;
    const uint32_t doff = (uint32_t)(lrow * ROWB + lc * 16);
    const size_t xbase = (size_t)(m0 + lrow) * K_ + lc * 8;
    const size_t wbase = (size_t)(n0 + lrow) * K_ + lc * 8;

    auto load_stage = [&](int kt, int slot) {
        const uint32_t sb = sbase + slot * STAGE;
        const int k0 = kt * BK;
        cp16(sb + OXH + doff, g_xh  + xbase + k0);
        cp16(sb + OXL + doff, g_xl  + xbase + k0);
        cp16(sb + OGH + doff, g_wgh + wbase + k0);
        cp16(sb + OGL + doff, g_wgl + wbase + k0);
        cp16(sb + OHH + doff, g_whh + wbase + k0);
        cp16(sb + OHL + doff, g_whl + wbase + k0);
        asm volatile("cp.async.commit_group;" ::: "memory");
    };

    load_stage(0, 0);
    load_stage(1, 1);

#pragma unroll 1
    for (int kt = 0; kt < NKT; ++kt) {
        if (kt + 1 < NKT)
            asm volatile("cp.async.wait_group 1;" ::: "memory");
        else
            asm volatile("cp.async.wait_group 0;" ::: "memory");
        __syncthreads();

        if (kt + 2 < NKT)
            load_stage(kt + 2, (kt + 2) % NSTAGE);

        const uint32_t sb = sbase + (kt % NSTAGE) * STAGE;
#pragma unroll
        for (int kk = 0; kk < 2; ++kk) {
            const uint32_t kb = kk * 32;
            uint32_t Ah[2][4], Al[2][4];
#pragma unroll
            for (int h = 0; h < 2; ++h) {
                ldsm4(Ah[h], sb + OXH + aoff + h * (16 * ROWB) + kb);
                ldsm4(Al[h], sb + OXL + aoff + h * (16 * ROWB) + kb);
            }
            uint32_t Gh[4], Gl[4], Hh[4], Hl[4];
            ldsm4(Gh, sb + OGH + boff + kb);
            ldsm4(Gl, sb + OGL + boff + kb);
            ldsm4(Hh, sb + OHH + boff + kb);
            ldsm4(Hl, sb + OHL + boff + kb);
#pragma unroll
            for (int h = 0; h < 2; ++h)
#pragma unroll
                for (int q = 0; q < 2; ++q) {
                    mma_bf16(accG[h][q], Ah[h], Gh + 2 * q);
                    mma_bf16(accG[h][q], Ah[h], Gl + 2 * q);
                    mma_bf16(accG[h][q], Al[h], Gh + 2 * q);
                    mma_bf16(accH[h][q], Ah[h], Hh + 2 * q);
                    mma_bf16(accH[h][q], Ah[h], Hl + 2 * q);
                    mma_bf16(accH[h][q], Al[h], Hh + 2 * q);
                }
        }
    }
    __syncthreads();

    // ---------------- epilogue: activations, staging, segment fold ----------
    float* sa  = (float*)smem;                         // 64 x EPS
    float* sbf = (float*)(smem + 64 * EPS * 4);        // 64 x EPS
    float* fA  = (float*)(smem + 2 * 64 * EPS * 4);    // 4 x 64
    float* fB  = fA + 4 * 64;

#pragma unroll
    for (int h = 0; h < 2; ++h)
#pragma unroll
        for (int q = 0; q < 2; ++q) {
            const int r0  = warpM * 32 + h * 16 + (lane >> 2);
            const int col = warpN * 16 + q * 8 + 2 * (lane & 3);
            const float bg0 = s_bg[col], bg1 = s_bg[col + 1];
            const float bh0 = s_bh[col], bh1 = s_bh[col + 1];
#pragma unroll
            for (int p = 0; p < 2; ++p) {
                const int row = r0 + p * 8;
                const float G0 = accG[h][q][2*p + 0] + bg0;
                const float G1 = accG[h][q][2*p + 1] + bg1;
                const float H0 = accH[h][q][2*p + 0] + bh0;
                const float H1 = accH[h][q][2*p + 1] + bh1;
                const float a0 = __fdividef(1.0f, 1.0f + __expf(-G0));
                const float a1 = __fdividef(1.0f, 1.0f + __expf(-G1));
                const float c0 = __fdividef(2.0f, 1.0f + __expf(-2.0f * H0)) - 1.0f;
                const float c1 = __fdividef(2.0f, 1.0f + __expf(-2.0f * H1)) - 1.0f;
                *(float2*)(sa  + row * EPS + col) = make_float2(a0, a1);
                *(float2*)(sbf + row * EPS + col) = make_float2((1.0f - a0) * c0,
                                                                (1.0f - a1) * c1);
            }
        }
    __syncthreads();

    // coalesced global stores of a/b
#pragma unroll
    for (int i = 0; i < 4; ++i) {
        const int id = i * NTH + tid;              // 0..1023
        const int row = id >> 4, slot = id & 15;
        const size_t o = (size_t)(m0 + row) * D_ + n0 + slot * 4;
        *(float4*)(g_a + o) = *(float4*)(sa  + row * EPS + slot * 4);
        *(float4*)(g_b + o) = *(float4*)(sbf + row * EPS + slot * 4);
    }

    // fused segment reduction: rows m0..m0+63 = one sub-segment (b, s)
    {
        const int c  = tid & 63;
        const int rb = tid >> 6;                   // 4 row-blocks of 16
        float A = 1.f, Bv = 0.f;
#pragma unroll
        for (int r = rb * 16; r < rb * 16 + 16; ++r) {
            const float a  = sa[r * EPS + c];
            const float bb = sbf[r * EPS + c];
            Bv = fmaf(a, Bv, bb);
            A *= a;
        }
        fA[rb * 64 + c] = A;
        fB[rb * 64 + c] = Bv;
    }
    __syncthreads();
    if (tid < 64) {
        float A = 1.f, Bv = 0.f;
#pragma unroll
        for (int j = 0; j < 4; ++j) {
            const float Aj = fA[j * 64 + tid];
            const float Bj = fB[j * 64 + tid];
            Bv = fmaf(Aj, Bv, Bj);
            A *= Aj;
        }
        const int b = m0 >> 12;                    // m0 / 4096
        const int s = (m0 & 4095) >> 6;            // sub-segment of 64
        const size_t o = ((size_t)(b * NSEG + s)) * D_ + n0 + tid;
        g_sA[o] = A;
        g_sB[o] = Bv;
    }
}

// ---------------------------------------------------------------------------
// Scan pass 2: exclusive prefix over the 64 segments per (b,d) channel
// ---------------------------------------------------------------------------
__global__ void scan_prefix()
{
    const int idx = blockIdx.x * blockDim.x + threadIdx.x;
    const int b = idx >> 10;
    const int d = idx & (D_ - 1);

    float PA = 1.f, PB = 0.f;
#pragma unroll
    for (int s = 0; s < NSEG; ++s) {
        const size_t o = ((size_t)(b * NSEG + s)) * D_ + d;
        g_pA[o] = PA;
        g_pB[o] = PB;
        const float A  = g_sA[o];
        const float Bs = g_sB[o];
        PB = fmaf(A, PB, Bs);
        PA = PA * A;
    }
}

// ---------------------------------------------------------------------------
// Scan pass 3: apply prefix, write h_t
// ---------------------------------------------------------------------------
__global__ void scan_apply(const float* __restrict__ hidden,
                           float* __restrict__ out)
{
    const int d = blockIdx.x * blockDim.x + threadIdx.x;
    const int s = blockIdx.y;
    const int b = blockIdx.z;

    const size_t po = ((size_t)(b * NSEG + s)) * D_ + d;
    float h = fmaf(g_pA[po], hidden[(size_t)b * D_ + d], g_pB[po]);

    size_t base = ((size_t)(b * L_ + s * TSEG)) * D_ + d;
#pragma unroll 8
    for (int t = 0; t < TSEG; ++t) {
        const float a  = g_a[base];
        const float bb = g_b[base];
        h = fmaf(a, h, bb);
        out[base] = h;
        base += D_;
    }
}

// ---------------------------------------------------------------------------
extern "C" void kernel_launch(void* const* d_in, const int* in_sizes, int n_in,
                              void* d_out, int out_size)
{
    const float* x      = (const float*)d_in[0];
    const float* hidden = (const float*)d_in[1];
    const float* Wg     = (const float*)d_in[2];
    const float* bg     = (const float*)d_in[3];
    const float* Wh     = (const float*)d_in[4];
    const float* bh     = (const float*)d_in[5];
    float* out = (float*)d_out;

    // bf16 hi/lo splits
    split_kernel<<<(M_ * K_ / 4) / 256, 256>>>(x,  0, M_ * K_ / 4);
    split_kernel<<<(D_ * K_ / 4) / 256, 256>>>(Wg, 1, D_ * K_ / 4);
    split_kernel<<<(D_ * K_ / 4) / 256, 256>>>(Wh, 2, D_ * K_ / 4);

    // tensor-core dual GEMM + activations + segment reduction
    cudaFuncSetAttribute(gemm_mma, cudaFuncAttributeMaxDynamicSharedMemorySize, DYNSM);
    dim3 gg(D_ / BN, M_ / BM);          // (16, 512)
    gemm_mma<<<gg, NTH, DYNSM>>>(bg, bh);

    // scan
    scan_prefix<<<(B_ * D_) / 256, 256>>>();
    dim3 sg(D_ / 256, NSEG, B_);
    scan_apply<<<sg, 256>>>(hidden, out);
}

// round 10
// speedup vs baseline: 1.1396x; 1.1396x over previous
#include <cuda_runtime.h>
#include <cuda_bf16.h>
#include <math.h>
#include <stdint.h>

#define B_ 8
#define L_ 4096
#define D_ 1024
#define M_ (B_ * L_)      // 32768
#define K_ D_             // 1024

// GEMM tiling (HMMA warp-level) — R7 proven config
#define BM 128
#define BN 64             // per-output (G and H each) N tile
#define BK 64
#define NKT (K_ / BK)     // 16
#define NTH 256

#define ROWB 144          // padded SMEM row stride bytes (128B data + 16B pad)
#define XT_BYTES (128 * ROWB)            // 18432 (one x tile)
#define WT_BYTES (64 * ROWB)             // 9216  (one W tile)
#define STAGE (2 * XT_BYTES + 4 * WT_BYTES)  // 73728
#define DYNSM (2 * STAGE)                // 147456

// stage-internal offsets
#define OXH 0
#define OXL (XT_BYTES)
#define OGH (2 * XT_BYTES)
#define OGL (2 * XT_BYTES + 1 * WT_BYTES)
#define OHH (2 * XT_BYTES + 2 * WT_BYTES)
#define OHL (2 * XT_BYTES + 3 * WT_BYTES)

// epilogue SMEM staging stride (floats)
#define EPS 68

// scan segmentation: one GEMM M-tile (128 rows) = one segment
#define NSEG 32
#define TSEG (L_ / NSEG)  // 128

// ---------------- device scratch (no allocs allowed) ----------------
__device__ __nv_bfloat16 g_xh[(size_t)M_ * K_];
__device__ __nv_bfloat16 g_xl[(size_t)M_ * K_];
__device__ __nv_bfloat16 g_wgh[(size_t)D_ * K_];
__device__ __nv_bfloat16 g_wgl[(size_t)D_ * K_];
__device__ __nv_bfloat16 g_whh[(size_t)D_ * K_];
__device__ __nv_bfloat16 g_whl[(size_t)D_ * K_];
__device__ float g_a[(size_t)M_ * D_];
__device__ float g_b[(size_t)M_ * D_];
__device__ float g_sA[B_ * NSEG * D_];
__device__ float g_sB[B_ * NSEG * D_];
__device__ float g_pA[B_ * NSEG * D_];
__device__ float g_pB[B_ * NSEG * D_];

// ---------------- helpers ----------------
__device__ __forceinline__ uint32_t smem_u32(const void* p) {
    uint32_t a;
    asm("{ .reg .u64 t; cvta.to.shared.u64 t, %1; cvt.u32.u64 %0, t; }" : "=r"(a) : "l"(p));
    return a;
}
__device__ __forceinline__ void cp16(uint32_t dst, const void* src) {
    asm volatile("cp.async.cg.shared.global [%0], [%1], 16;" :: "r"(dst), "l"(src));
}
__device__ __forceinline__ void ldsm4(uint32_t* r, uint32_t addr) {
    asm volatile("ldmatrix.sync.aligned.m8n8.x4.shared.b16 {%0,%1,%2,%3}, [%4];"
                 : "=r"(r[0]), "=r"(r[1]), "=r"(r[2]), "=r"(r[3]) : "r"(addr));
}
__device__ __forceinline__ void mma_bf16(float* d, const uint32_t* a, const uint32_t* b) {
    asm volatile("mma.sync.aligned.m16n8k16.row.col.f32.bf16.bf16.f32 "
                 "{%0,%1,%2,%3}, {%4,%5,%6,%7}, {%8,%9}, {%0,%1,%2,%3};"
                 : "+f"(d[0]), "+f"(d[1]), "+f"(d[2]), "+f"(d[3])
                 : "r"(a[0]), "r"(a[1]), "r"(a[2]), "r"(a[3]), "r"(b[0]), "r"(b[1]));
}

// ---------------------------------------------------------------------------
// Split fp32 -> bf16 hi/lo. tag: 0=x, 1=Wg, 2=Wh
// ---------------------------------------------------------------------------
__global__ void split_kernel(const float* __restrict__ src, int tag, int n4)
{
    int i = blockIdx.x * blockDim.x + threadIdx.x;
    if (i >= n4) return;
    __nv_bfloat16* hi;
    __nv_bfloat16* lo;
    if (tag == 0)      { hi = g_xh;  lo = g_xl;  }
    else if (tag == 1) { hi = g_wgh; lo = g_wgl; }
    else               { hi = g_whh; lo = g_whl; }

    float4 v = ((const float4*)src)[i];
    float f[4] = {v.x, v.y, v.z, v.w};
    __nv_bfloat16 h[4], l[4];
#pragma unroll
    for (int j = 0; j < 4; ++j) {
        __nv_bfloat16 hb = __float2bfloat16(f[j]);
        h[j] = hb;
        l[j] = __float2bfloat16(f[j] - __bfloat162float(hb));
    }
    ((uint2*)hi)[i] = *(uint2*)h;
    ((uint2*)lo)[i] = *(uint2*)l;
}

// ---------------------------------------------------------------------------
// HMMA dual GEMM + activations + fused per-segment scan reduction
//   Dg = x @ Wg^T ; Dh = x @ Wh^T   (3-term bf16 split, fp32 accum)
//   a = sigmoid(Dg + bg) ; b = (1-a) * tanh(Dh + bh)
//   also emits (prod a, fold b) over the 128-row tile (= one segment)
// ---------------------------------------------------------------------------
__global__ void __launch_bounds__(NTH, 1)
gemm_mma(const float* __restrict__ bg, const float* __restrict__ bh)
{
    extern __shared__ char smem[];
    __shared__ float s_bg[BN], s_bh[BN];

    const int tid   = threadIdx.x;
    const int wid   = tid >> 5;
    const int lane  = tid & 31;
    const int warpM = wid & 3;         // 0..3 -> m rows 32*warpM
    const int warpN = wid >> 2;        // 0..1 -> n cols 32*warpN
    const int m0 = blockIdx.y * BM;
    const int n0 = blockIdx.x * BN;

    if (tid < BN)            s_bg[tid]      = bg[n0 + tid];
    else if (tid < 2 * BN)   s_bh[tid - BN] = bh[n0 + tid - BN];

    const uint32_t sbase = smem_u32(smem);

    // ldmatrix per-lane offsets
    const int mat = lane >> 3;
    const int lr  = lane & 7;
    // A x4: mats = (m0-7,k0-7),(m8-15,k0-7),(m0-7,k8-15),(m8-15,k8-15)
    const uint32_t aoff = (uint32_t)((warpM * 32 + (mat & 1) * 8 + lr) * ROWB + (mat >> 1) * 16);
    // B x4: mats = (n0-7,k0-7),(n0-7,k8-15),(n8-15,k0-7),(n8-15,k8-15)
    const uint32_t boff = (uint32_t)((warpN * 32 + (mat >> 1) * 8 + lr) * ROWB + (mat & 1) * 16);

    float accG[2][4][4], accH[2][4][4];
#pragma unroll
    for (int h = 0; h < 2; ++h)
#pragma unroll
        for (int nb = 0; nb < 4; ++nb)
#pragma unroll
            for (int r = 0; r < 4; ++r) { accG[h][nb][r] = 0.f; accH[h][nb][r] = 0.f; }

    auto load_stage = [&](int kt, int buf) {
        const uint32_t sb = sbase + buf * STAGE;
        const int k0 = kt * BK;
#pragma unroll
        for (int i = 0; i < 4; ++i) {
            const int id = i * NTH + tid;           // 0..1023
            const int row = id >> 3, c = id & 7;
            const size_t so = (size_t)(m0 + row) * K_ + k0 + c * 8;
            const uint32_t doff = (uint32_t)(row * ROWB + c * 16);
            cp16(sb + OXH + doff, g_xh + so);
            cp16(sb + OXL + doff, g_xl + so);
        }
#pragma unroll
        for (int i = 0; i < 2; ++i) {
            const int id = i * NTH + tid;           // 0..511
            const int row = id >> 3, c = id & 7;
            const size_t so = (size_t)(n0 + row) * K_ + k0 + c * 8;
            const uint32_t doff = (uint32_t)(row * ROWB + c * 16);
            cp16(sb + OGH + doff, g_wgh + so);
            cp16(sb + OGL + doff, g_wgl + so);
            cp16(sb + OHH + doff, g_whh + so);
            cp16(sb + OHL + doff, g_whl + so);
        }
        asm volatile("cp.async.commit_group;" ::: "memory");
    };

    load_stage(0, 0);

#pragma unroll 1
    for (int kt = 0; kt < NKT; ++kt) {
        const int buf = kt & 1;
        if (kt + 1 < NKT) {
            load_stage(kt + 1, buf ^ 1);
            asm volatile("cp.async.wait_group 1;" ::: "memory");
        } else {
            asm volatile("cp.async.wait_group 0;" ::: "memory");
        }
        __syncthreads();

        const uint32_t sb = sbase + buf * STAGE;
#pragma unroll
        for (int kk = 0; kk < 4; ++kk) {
            const uint32_t kb = kk * 32;
            uint32_t Ah[2][4], Al[2][4];
#pragma unroll
            for (int h = 0; h < 2; ++h) {
                ldsm4(Ah[h], sb + OXH + aoff + h * 16 * ROWB + kb);
                ldsm4(Al[h], sb + OXL + aoff + h * 16 * ROWB + kb);
            }
            uint32_t Gh[4][2], Gl[4][2], Hh[4][2], Hl[4][2];
#pragma unroll
            for (int q = 0; q < 2; ++q) {
                const uint32_t bq = boff + q * 16 * ROWB + kb;
                uint32_t t[4];
                ldsm4(t, sb + OGH + bq);
                Gh[2*q][0]=t[0]; Gh[2*q][1]=t[1]; Gh[2*q+1][0]=t[2]; Gh[2*q+1][1]=t[3];
                ldsm4(t, sb + OGL + bq);
                Gl[2*q][0]=t[0]; Gl[2*q][1]=t[1]; Gl[2*q+1][0]=t[2]; Gl[2*q+1][1]=t[3];
                ldsm4(t, sb + OHH + bq);
                Hh[2*q][0]=t[0]; Hh[2*q][1]=t[1]; Hh[2*q+1][0]=t[2]; Hh[2*q+1][1]=t[3];
                ldsm4(t, sb + OHL + bq);
                Hl[2*q][0]=t[0]; Hl[2*q][1]=t[1]; Hl[2*q+1][0]=t[2]; Hl[2*q+1][1]=t[3];
            }
#pragma unroll
            for (int h = 0; h < 2; ++h)
#pragma unroll
                for (int nb = 0; nb < 4; ++nb) {
                    mma_bf16(accG[h][nb], Ah[h], Gh[nb]);
                    mma_bf16(accG[h][nb], Ah[h], Gl[nb]);
                    mma_bf16(accG[h][nb], Al[h], Gh[nb]);
                    mma_bf16(accH[h][nb], Ah[h], Hh[nb]);
                    mma_bf16(accH[h][nb], Ah[h], Hl[nb]);
                    mma_bf16(accH[h][nb], Al[h], Hh[nb]);
                }
        }
        __syncthreads();
    }

    // ---------------- epilogue: activations + coalesced stores ----------------
    float* sa  = (float*)smem;                       // 128 x EPS fp32
    float* sbf = (float*)(smem + 128 * EPS * 4);     // 128 x EPS fp32
    float* fA  = (float*)(smem + 2 * 128 * EPS * 4); // 4 x 64
    float* fB  = fA + 4 * 64;

#pragma unroll
    for (int h = 0; h < 2; ++h)
#pragma unroll
        for (int nb = 0; nb < 4; ++nb) {
            const int r0  = warpM * 32 + h * 16 + (lane >> 2);
            const int col = warpN * 32 + nb * 8 + 2 * (lane & 3);
            const float bg0 = s_bg[col], bg1 = s_bg[col + 1];
            const float bh0 = s_bh[col], bh1 = s_bh[col + 1];
#pragma unroll
            for (int p = 0; p < 2; ++p) {            // p=0: row r0, p=1: row r0+8
                const int row = r0 + p * 8;
                const float G0 = accG[h][nb][2*p + 0] + bg0;
                const float G1 = accG[h][nb][2*p + 1] + bg1;
                const float H0 = accH[h][nb][2*p + 0] + bh0;
                const float H1 = accH[h][nb][2*p + 1] + bh1;
                const float a0 = __fdividef(1.0f, 1.0f + __expf(-G0));
                const float a1 = __fdividef(1.0f, 1.0f + __expf(-G1));
                const float c0 = __fdividef(2.0f, 1.0f + __expf(-2.0f * H0)) - 1.0f;
                const float c1 = __fdividef(2.0f, 1.0f + __expf(-2.0f * H1)) - 1.0f;
                float2 av = make_float2(a0, a1);
                float2 bv = make_float2((1.0f - a0) * c0, (1.0f - a1) * c1);
                *(float2*)(sa  + row * EPS + col) = av;
                *(float2*)(sbf + row * EPS + col) = bv;
            }
        }
    __syncthreads();

#pragma unroll
    for (int i = 0; i < 8; ++i) {
        const int id = i * NTH + tid;                // 0..2047
        const int row = id >> 4, slot = id & 15;
        const size_t o = (size_t)(m0 + row) * D_ + n0 + slot * 4;
        *(float4*)(g_a + o) = *(float4*)(sa  + row * EPS + slot * 4);
        *(float4*)(g_b + o) = *(float4*)(sbf + row * EPS + slot * 4);
    }

    // fused segment reduction: rows m0..m0+127 = one segment (b, s)
    {
        const int c  = tid & 63;
        const int rb = tid >> 6;                     // 4 row-blocks of 32
        float A = 1.f, Bv = 0.f;
#pragma unroll
        for (int r = rb * 32; r < rb * 32 + 32; ++r) {
            const float a  = sa[r * EPS + c];
            const float bb = sbf[r * EPS + c];
            Bv = fmaf(a, Bv, bb);
            A *= a;
        }
        fA[rb * 64 + c] = A;
        fB[rb * 64 + c] = Bv;
    }
    __syncthreads();
    if (tid < 64) {
        float A = 1.f, Bv = 0.f;
#pragma unroll
        for (int j = 0; j < 4; ++j) {
            const float Aj = fA[j * 64 + tid];
            const float Bj = fB[j * 64 + tid];
            Bv = fmaf(Aj, Bv, Bj);
            A *= Aj;
        }
        const int b = m0 >> 12;                      // m0 / 4096
        const int s = (m0 & 4095) >> 7;              // segment of 128
        const size_t o = ((size_t)(b * NSEG + s)) * D_ + n0 + tid;
        g_sA[o] = A;
        g_sB[o] = Bv;
    }
}

// ---------------------------------------------------------------------------
// Scan pass 2: exclusive prefix over the 32 segments per (b,d) channel
// ---------------------------------------------------------------------------
__global__ void scan_prefix()
{
    const int idx = blockIdx.x * blockDim.x + threadIdx.x;
    const int b = idx >> 10;
    const int d = idx & (D_ - 1);

    float PA = 1.f, PB = 0.f;
#pragma unroll
    for (int s = 0; s < NSEG; ++s) {
        const size_t o = ((size_t)(b * NSEG + s)) * D_ + d;
        g_pA[o] = PA;
        g_pB[o] = PB;
        const float A  = g_sA[o];
        const float Bs = g_sB[o];
        PB = fmaf(A, PB, Bs);
        PA = PA * A;
    }
}

// ---------------------------------------------------------------------------
// Scan pass 3: apply prefix, write h_t
// ---------------------------------------------------------------------------
__global__ void scan_apply(const float* __restrict__ hidden,
                           float* __restrict__ out)
{
    const int d = blockIdx.x * blockDim.x + threadIdx.x;
    const int s = blockIdx.y;
    const int b = blockIdx.z;

    const size_t po = ((size_t)(b * NSEG + s)) * D_ + d;
    float h = fmaf(g_pA[po], hidden[(size_t)b * D_ + d], g_pB[po]);

    size_t base = ((size_t)(b * L_ + s * TSEG)) * D_ + d;
#pragma unroll 8
    for (int t = 0; t < TSEG; ++t) {
        const float a  = g_a[base];
        const float bb = g_b[base];
        h = fmaf(a, h, bb);
        out[base] = h;
        base += D_;
    }
}

// ---------------------------------------------------------------------------
extern "C" void kernel_launch(void* const* d_in, const int* in_sizes, int n_in,
                              void* d_out, int out_size)
{
    const float* x      = (const float*)d_in[0];
    const float* hidden = (const float*)d_in[1];
    const float* Wg     = (const float*)d_in[2];
    const float* bg     = (const float*)d_in[3];
    const float* Wh     = (const float*)d_in[4];
    const float* bh     = (const float*)d_in[5];
    float* out = (float*)d_out;

    // bf16 hi/lo splits
    split_kernel<<<(M_ * K_ / 4) / 256, 256>>>(x,  0, M_ * K_ / 4);
    split_kernel<<<(D_ * K_ / 4) / 256, 256>>>(Wg, 1, D_ * K_ / 4);
    split_kernel<<<(D_ * K_ / 4) / 256, 256>>>(Wh, 2, D_ * K_ / 4);

    // tensor-core dual GEMM + activations + fused segment reduction
    cudaFuncSetAttribute(gemm_mma, cudaFuncAttributeMaxDynamicSharedMemorySize, DYNSM);
    dim3 gg(D_ / BN, M_ / BM);          // (16, 256)
    gemm_mma<<<gg, NTH, DYNSM>>>(bg, bh);

    // scan
    scan_prefix<<<(B_ * D_) / 256, 256>>>();
    dim3 sg(D_ / 256, NSEG, B_);
    scan_apply<<<sg, 256>>>(hidden, out);
}